// round 12
// baseline (speedup 1.0000x reference)
#include <cuda_runtime.h>
#include <cuda_bf16.h>
#include <cstdint>

// y[b, f*C + c] = sum_hw x[b,c,hw] * kern[f,c,hw]
// B=256, F=16, C=256, HW=1024
// Grid: (C=256, KSPLIT=8) = 2048 CTAs (wave-balance: ~2.77 waves @5 CTAs/SM
// instead of 1.38 -> kills the starved second-wave tail seen in R7).
// Block: 128 threads; thread = TWO b rows (t, t+128): each ks broadcast feeds
// 16 FMA2. Split-K partials combined via atomicAdd after zero-init.
// x staged global->smem via cp.async, double-buffered; fma.rn.f32x2 compute.

#define B_DIM 256
#define F_DIM 16
#define C_DIM 256
#define HW_DIM 1024

#define KC 16
#define THREADS 128
#define XS_PITCH 20                   // floats; conflict-free LDS.128 pattern
#define KSPLIT 8
#define KSLICE (HW_DIM / KSPLIT)      // 128
#define NCHUNK (KSLICE / KC)          // 8

static_assert(HW_DIM % KSPLIT == 0 && KSLICE % KC == 0 && NCHUNK >= 2,
              "pipeline invariants");

__device__ __forceinline__ unsigned long long fma2(unsigned long long a,
                                                   unsigned long long b,
                                                   unsigned long long c) {
    unsigned long long d;
    asm("fma.rn.f32x2 %0, %1, %2, %3;" : "=l"(d) : "l"(a), "l"(b), "l"(c));
    return d;
}

__device__ __forceinline__ unsigned long long dup2(float v) {
    unsigned long long d;
    asm("mov.b64 %0, {%1, %1};" : "=l"(d) : "f"(v));
    return d;
}

__global__ void zero_kernel(float* __restrict__ out, int n) {
    for (int i = blockIdx.x * blockDim.x + threadIdx.x; i < n;
         i += gridDim.x * blockDim.x)
        out[i] = 0.0f;
}

__global__ __launch_bounds__(THREADS, 5)
void spatial_emb_kernel(const float* __restrict__ x,
                        const float* __restrict__ kern,
                        float* __restrict__ out) {
    const int c  = blockIdx.x;          // channel
    const int kh = blockIdx.y;          // k slice
    const int t  = threadIdx.x;

    __shared__ float xs[2][B_DIM][XS_PITCH];  // [buf][b][k]  40 KB
    __shared__ float ks[2][KC][F_DIM];        // [buf][k][f]   2 KB

    // x staging: 8 iterations; it covers rows xr + it*32 at cols xc..xc+3.
    const int xr = t >> 2;              // 0..31
    const int xc = (t & 3) * 4;         // 0,4,8,12
    const float* xg = x + ((size_t)xr * C_DIM + c) * HW_DIM
                        + (size_t)kh * KSLICE + xc;
    const size_t xrs = (size_t)32 * C_DIM * HW_DIM;   // 32 b-rows

    // k staging: thread -> f = t>>3, k-cols kk, kk+1 (transposed store)
    const int kf = t >> 3;              // 0..15
    const int kk = (t & 7) * 2;         // 0..14
    const float* kg = kern + ((size_t)kf * C_DIM + c) * HW_DIM
                           + (size_t)kh * KSLICE + kk;

    unsigned long long accA[8], accB[8];   // rows t and t+128, 16 f each
    #pragma unroll
    for (int j = 0; j < 8; j++) { accA[j] = 0ull; accB[j] = 0ull; }

    // ---- prologue: chunk 0 cp.async in flight; chunk 1 k-frag in regs
    {
        #pragma unroll
        for (int it = 0; it < 8; it++) {
            uint32_t dst = (uint32_t)__cvta_generic_to_shared(&xs[0][xr + it * 32][xc]);
            const float* src = xg + it * xrs;
            asm volatile("cp.async.cg.shared.global [%0], [%1], 16;\n"
                         :: "r"(dst), "l"(src));
        }
        asm volatile("cp.async.commit_group;\n");
    }
    float2 kv = *(const float2*)kg;           // chunk 0 frag
    ks[0][kk + 0][kf] = kv.x;
    ks[0][kk + 1][kf] = kv.y;
    kv = *(const float2*)(kg + KC);           // chunk 1 frag

    int buf = 0;
    for (int ch = 0; ch < NCHUNK; ch++) {
        asm volatile("cp.async.wait_group 0;\n" ::: "memory");
        __syncthreads();   // chunk ch visible; all threads done with ch-1

        if (ch + 1 < NCHUNK) {
            #pragma unroll
            for (int it = 0; it < 8; it++) {
                uint32_t dst = (uint32_t)__cvta_generic_to_shared(&xs[buf ^ 1][xr + it * 32][xc]);
                const float* src = xg + (size_t)(ch + 1) * KC + it * xrs;
                asm volatile("cp.async.cg.shared.global [%0], [%1], 16;\n"
                             :: "r"(dst), "l"(src));
            }
            asm volatile("cp.async.commit_group;\n");
            ks[buf ^ 1][kk + 0][kf] = kv.x;
            ks[buf ^ 1][kk + 1][kf] = kv.y;
            if (ch + 2 < NCHUNK)
                kv = *(const float2*)(kg + (size_t)(ch + 2) * KC);
        }

        // ---- compute chunk ch: thread t handles b rows t and t+128
        #pragma unroll
        for (int k4 = 0; k4 < KC / 4; k4++) {
            float4 xfa = *(const float4*)&xs[buf][t      ][k4 * 4];
            float4 xfb = *(const float4*)&xs[buf][t + 128][k4 * 4];
            #pragma unroll
            for (int j = 0; j < 4; j++) {
                const int k = k4 * 4 + j;
                float va = (j == 0) ? xfa.x : (j == 1) ? xfa.y : (j == 2) ? xfa.z : xfa.w;
                float vb = (j == 0) ? xfb.x : (j == 1) ? xfb.y : (j == 2) ? xfb.z : xfb.w;
                unsigned long long xa = dup2(va);
                unsigned long long xb = dup2(vb);
                ulonglong2 p0 = *(const ulonglong2*)&ks[buf][k][0];
                ulonglong2 p1 = *(const ulonglong2*)&ks[buf][k][4];
                ulonglong2 p2 = *(const ulonglong2*)&ks[buf][k][8];
                ulonglong2 p3 = *(const ulonglong2*)&ks[buf][k][12];
                accA[0] = fma2(xa, p0.x, accA[0]);  accB[0] = fma2(xb, p0.x, accB[0]);
                accA[1] = fma2(xa, p0.y, accA[1]);  accB[1] = fma2(xb, p0.y, accB[1]);
                accA[2] = fma2(xa, p1.x, accA[2]);  accB[2] = fma2(xb, p1.x, accB[2]);
                accA[3] = fma2(xa, p1.y, accA[3]);  accB[3] = fma2(xb, p1.y, accB[3]);
                accA[4] = fma2(xa, p2.x, accA[4]);  accB[4] = fma2(xb, p2.x, accB[4]);
                accA[5] = fma2(xa, p2.y, accA[5]);  accB[5] = fma2(xb, p2.y, accB[5]);
                accA[6] = fma2(xa, p3.x, accA[6]);  accB[6] = fma2(xb, p3.x, accB[6]);
                accA[7] = fma2(xa, p3.y, accA[7]);  accB[7] = fma2(xb, p3.y, accB[7]);
            }
        }
        buf ^= 1;
    }

    // ---- output: split-K partials combined with atomicAdd (REDG)
    float* orowA = out + (size_t)t * (F_DIM * C_DIM) + c;
    float* orowB = out + (size_t)(t + 128) * (F_DIM * C_DIM) + c;
    #pragma unroll
    for (int j = 0; j < 8; j++) {
        unsigned int lo, hi;
        asm("mov.b64 {%0, %1}, %2;" : "=r"(lo), "=r"(hi) : "l"(accA[j]));
        atomicAdd(&orowA[(size_t)(2 * j + 0) * C_DIM], __uint_as_float(lo));
        atomicAdd(&orowA[(size_t)(2 * j + 1) * C_DIM], __uint_as_float(hi));
        asm("mov.b64 {%0, %1}, %2;" : "=r"(lo), "=r"(hi) : "l"(accB[j]));
        atomicAdd(&orowB[(size_t)(2 * j + 0) * C_DIM], __uint_as_float(lo));
        atomicAdd(&orowB[(size_t)(2 * j + 1) * C_DIM], __uint_as_float(hi));
    }
}

extern "C" void kernel_launch(void* const* d_in, const int* in_sizes, int n_in,
                              void* d_out, int out_size) {
    const float* x    = (const float*)d_in[0];
    const float* kern = (const float*)d_in[1];
    float* out        = (float*)d_out;

    zero_kernel<<<512, 256>>>(out, out_size);

    dim3 grid(C_DIM, KSPLIT);   // (256, 8)
    spatial_emb_kernel<<<grid, THREADS>>>(x, kern, out);
}

// round 13
// speedup vs baseline: 1.1480x; 1.1480x over previous
#include <cuda_runtime.h>
#include <cuda_bf16.h>
#include <cstdint>

// y[b, f*C + c] = sum_hw x[b,c,hw] * kern[f,c,hw]
// B=256, F=16, C=256, HW=1024
// Grid: (C=256, KSPLIT=4). Block: 128 threads.
// Thread tile: 4 b-rows (tb, tb+64, tb+128, tb+192) x 8 f (warp-uniform half):
// per k-step 16 FMA2 vs only 3 LDS (2 broadcast ks + 1 amortized x).
// Split-K partials combined via atomicAdd after zero-init.
// x staged global->smem via cp.async, double-buffered; fma.rn.f32x2 compute.

#define B_DIM 256
#define F_DIM 16
#define C_DIM 256
#define HW_DIM 1024

#define KC 16
#define THREADS 128
#define XS_PITCH 20                   // floats; verified conflict-free LDS.128
#define KSPLIT 4
#define KSLICE (HW_DIM / KSPLIT)      // 256
#define NCHUNK (KSLICE / KC)          // 16

static_assert(HW_DIM % KSPLIT == 0 && KSLICE % KC == 0 && NCHUNK >= 2,
              "pipeline invariants");

__device__ __forceinline__ unsigned long long fma2(unsigned long long a,
                                                   unsigned long long b,
                                                   unsigned long long c) {
    unsigned long long d;
    asm("fma.rn.f32x2 %0, %1, %2, %3;" : "=l"(d) : "l"(a), "l"(b), "l"(c));
    return d;
}

__device__ __forceinline__ unsigned long long dup2(float v) {
    unsigned long long d;
    asm("mov.b64 %0, {%1, %1};" : "=l"(d) : "f"(v));
    return d;
}

__global__ void zero_kernel(float* __restrict__ out, int n) {
    for (int i = blockIdx.x * blockDim.x + threadIdx.x; i < n;
         i += gridDim.x * blockDim.x)
        out[i] = 0.0f;
}

__global__ __launch_bounds__(THREADS, 5)
void spatial_emb_kernel(const float* __restrict__ x,
                        const float* __restrict__ kern,
                        float* __restrict__ out) {
    const int c  = blockIdx.x;          // channel
    const int kh = blockIdx.y;          // k slice
    const int t  = threadIdx.x;

    __shared__ float xs[2][B_DIM][XS_PITCH];  // [buf][b][k]  40 KB
    __shared__ float ks[2][KC][F_DIM];        // [buf][k][f]   2 KB

    // x staging: 8 iterations; it covers rows xr + it*32 at cols xc..xc+3.
    const int xr = t >> 2;              // 0..31
    const int xc = (t & 3) * 4;         // 0,4,8,12
    const float* xg = x + ((size_t)xr * C_DIM + c) * HW_DIM
                        + (size_t)kh * KSLICE + xc;
    const size_t xrs = (size_t)32 * C_DIM * HW_DIM;   // 32 b-rows

    // k staging: thread -> f = t>>3, k-cols kk, kk+1 (transposed store)
    const int kf = t >> 3;              // 0..15
    const int kk = (t & 7) * 2;         // 0..14
    const float* kg = kern + ((size_t)kf * C_DIM + c) * HW_DIM
                           + (size_t)kh * KSLICE + kk;

    // Compute roles: f-half is warp-uniform; 4 b-rows per thread.
    const int fh = t >> 6;              // 0 or 1 -> f base fh*8
    const int tb = t & 63;              // rows tb + {0,64,128,192}

    unsigned long long acc[4][4];       // [row][f-pair], 8 f per row
    #pragma unroll
    for (int r = 0; r < 4; r++)
        #pragma unroll
        for (int j = 0; j < 4; j++)
            acc[r][j] = 0ull;

    // ---- prologue: chunk 0 cp.async in flight; chunk 1 k-frag in regs
    {
        #pragma unroll
        for (int it = 0; it < 8; it++) {
            uint32_t dst = (uint32_t)__cvta_generic_to_shared(&xs[0][xr + it * 32][xc]);
            const float* src = xg + it * xrs;
            asm volatile("cp.async.cg.shared.global [%0], [%1], 16;\n"
                         :: "r"(dst), "l"(src));
        }
        asm volatile("cp.async.commit_group;\n");
    }
    float2 kv = *(const float2*)kg;           // chunk 0 frag
    ks[0][kk + 0][kf] = kv.x;
    ks[0][kk + 1][kf] = kv.y;
    kv = *(const float2*)(kg + KC);           // chunk 1 frag

    int buf = 0;
    for (int ch = 0; ch < NCHUNK; ch++) {
        asm volatile("cp.async.wait_group 0;\n" ::: "memory");
        __syncthreads();   // chunk ch visible; all threads done with ch-1

        if (ch + 1 < NCHUNK) {
            #pragma unroll
            for (int it = 0; it < 8; it++) {
                uint32_t dst = (uint32_t)__cvta_generic_to_shared(&xs[buf ^ 1][xr + it * 32][xc]);
                const float* src = xg + (size_t)(ch + 1) * KC + it * xrs;
                asm volatile("cp.async.cg.shared.global [%0], [%1], 16;\n"
                             :: "r"(dst), "l"(src));
            }
            asm volatile("cp.async.commit_group;\n");
            ks[buf ^ 1][kk + 0][kf] = kv.x;
            ks[buf ^ 1][kk + 1][kf] = kv.y;
            if (ch + 2 < NCHUNK)
                kv = *(const float2*)(kg + (size_t)(ch + 2) * KC);
        }

        // ---- compute chunk ch: 4 b-rows x 8 f per thread
        #pragma unroll
        for (int k4 = 0; k4 < KC / 4; k4++) {
            float4 xf0 = *(const float4*)&xs[buf][tb      ][k4 * 4];
            float4 xf1 = *(const float4*)&xs[buf][tb + 64 ][k4 * 4];
            float4 xf2 = *(const float4*)&xs[buf][tb + 128][k4 * 4];
            float4 xf3 = *(const float4*)&xs[buf][tb + 192][k4 * 4];
            #pragma unroll
            for (int j = 0; j < 4; j++) {
                const int k = k4 * 4 + j;
                ulonglong2 p0 = *(const ulonglong2*)&ks[buf][k][fh * 8];
                ulonglong2 p1 = *(const ulonglong2*)&ks[buf][k][fh * 8 + 4];
                float v0 = (j == 0) ? xf0.x : (j == 1) ? xf0.y : (j == 2) ? xf0.z : xf0.w;
                float v1 = (j == 0) ? xf1.x : (j == 1) ? xf1.y : (j == 2) ? xf1.z : xf1.w;
                float v2 = (j == 0) ? xf2.x : (j == 1) ? xf2.y : (j == 2) ? xf2.z : xf2.w;
                float v3 = (j == 0) ? xf3.x : (j == 1) ? xf3.y : (j == 2) ? xf3.z : xf3.w;
                unsigned long long a0 = dup2(v0);
                unsigned long long a1 = dup2(v1);
                unsigned long long a2 = dup2(v2);
                unsigned long long a3 = dup2(v3);
                acc[0][0] = fma2(a0, p0.x, acc[0][0]);
                acc[0][1] = fma2(a0, p0.y, acc[0][1]);
                acc[0][2] = fma2(a0, p1.x, acc[0][2]);
                acc[0][3] = fma2(a0, p1.y, acc[0][3]);
                acc[1][0] = fma2(a1, p0.x, acc[1][0]);
                acc[1][1] = fma2(a1, p0.y, acc[1][1]);
                acc[1][2] = fma2(a1, p1.x, acc[1][2]);
                acc[1][3] = fma2(a1, p1.y, acc[1][3]);
                acc[2][0] = fma2(a2, p0.x, acc[2][0]);
                acc[2][1] = fma2(a2, p0.y, acc[2][1]);
                acc[2][2] = fma2(a2, p1.x, acc[2][2]);
                acc[2][3] = fma2(a2, p1.y, acc[2][3]);
                acc[3][0] = fma2(a3, p0.x, acc[3][0]);
                acc[3][1] = fma2(a3, p0.y, acc[3][1]);
                acc[3][2] = fma2(a3, p1.x, acc[3][2]);
                acc[3][3] = fma2(a3, p1.y, acc[3][3]);
            }
        }
        buf ^= 1;
    }

    // ---- output: split-K partials combined with atomicAdd (REDG)
    #pragma unroll
    for (int r = 0; r < 4; r++) {
        const int b = tb + r * 64;
        float* orow = out + (size_t)b * (F_DIM * C_DIM) + c;
        #pragma unroll
        for (int j = 0; j < 4; j++) {
            const int f = fh * 8 + 2 * j;
            unsigned int lo, hi;
            asm("mov.b64 {%0, %1}, %2;" : "=r"(lo), "=r"(hi) : "l"(acc[r][j]));
            atomicAdd(&orow[(size_t)(f + 0) * C_DIM], __uint_as_float(lo));
            atomicAdd(&orow[(size_t)(f + 1) * C_DIM], __uint_as_float(hi));
        }
    }
}

extern "C" void kernel_launch(void* const* d_in, const int* in_sizes, int n_in,
                              void* d_out, int out_size) {
    const float* x    = (const float*)d_in[0];
    const float* kern = (const float*)d_in[1];
    float* out        = (float*)d_out;

    zero_kernel<<<512, 256>>>(out, out_size);

    dim3 grid(C_DIM, KSPLIT);   // (256, 4)
    spatial_emb_kernel<<<grid, THREADS>>>(x, kern, out);
}

// round 16
// speedup vs baseline: 1.4768x; 1.2865x over previous
#include <cuda_runtime.h>
#include <cuda_bf16.h>
#include <cstdint>

// y[b, f*C + c] = sum_hw x[b,c,hw] * kern[f,c,hw]
// B=256, F=16, C=256, HW=1024
// Grid (C=256, 2 b-halves), 128 threads (4 warps). Per CTA: GEMM M=128, N=16,
// K=1024 via warp-level mma.sync.m16n8k16 (bf16 in, fp32 accum) — base-target
// PTX (tcgen05 unavailable: harness compiles PTX at compute_103, no 'a').
// Precision: 2-term bf16 split of both operands, 3 MMAs per k-step
// (hi*hi + lo*hi + hi*lo) -> rel err ~1e-5.
// K chunks of 32 staged f32->bf16 in smem; pitch 80B (5x16B, gcd(5,8)=1) makes
// LDSM conflict-free without swizzle. Register prefetch overlaps global loads
// with MMA compute. Warp w owns b-rows w*32..w*32+31 (2 m16 tiles x 2 n8).

#define B_DIM 256
#define F_DIM 16
#define C_DIM 256
#define HW_DIM 1024
#define KC 32
#define NCH (HW_DIM / KC)      // 32
#define THREADS 128

#define XPITCH 80              // bytes per tile row (64B data + 16B pad)
#define XHI 0                  // x hi tile: 128 rows * 80B = 10240
#define XLO 10240
#define KHI 20480              // k tiles: 16 rows * 80B = 1280
#define KLO 21760
#define SMEM_BYTES 23040

__device__ __forceinline__ uint32_t smem_u32(const void* p) {
    uint32_t a;
    asm("{ .reg .u64 t; cvta.to.shared.u64 t, %1; cvt.u32.u64 %0, t; }"
        : "=r"(a) : "l"(p));
    return a;
}

// split two floats -> packed bf16x2 hi (lo-half = first arg) + packed bf16x2 lo-residual
__device__ __forceinline__ void split2(float a, float b, uint32_t& hp, uint32_t& lp) {
    __nv_bfloat16 ha = __float2bfloat16_rn(a);
    __nv_bfloat16 hb = __float2bfloat16_rn(b);
    float la = a - __bfloat162float(ha);
    float lb = b - __bfloat162float(hb);
    __nv_bfloat162 h2 = __halves2bfloat162(ha, hb);
    __nv_bfloat162 l2 = __halves2bfloat162(__float2bfloat16_rn(la),
                                           __float2bfloat16_rn(lb));
    hp = *reinterpret_cast<uint32_t*>(&h2);
    lp = *reinterpret_cast<uint32_t*>(&l2);
}

__device__ __forceinline__ void ldsm4(uint32_t (&r)[4], uint32_t addr) {
    asm volatile("ldmatrix.sync.aligned.m8n8.x4.shared.b16 {%0,%1,%2,%3}, [%4];"
                 : "=r"(r[0]), "=r"(r[1]), "=r"(r[2]), "=r"(r[3]) : "r"(addr));
}

__device__ __forceinline__ void mma16816(float (&d)[4], const uint32_t (&a)[4],
                                         uint32_t b0, uint32_t b1) {
    asm volatile(
        "mma.sync.aligned.m16n8k16.row.col.f32.bf16.bf16.f32 "
        "{%0,%1,%2,%3}, {%4,%5,%6,%7}, {%8,%9}, {%0,%1,%2,%3};"
        : "+f"(d[0]), "+f"(d[1]), "+f"(d[2]), "+f"(d[3])
        : "r"(a[0]), "r"(a[1]), "r"(a[2]), "r"(a[3]), "r"(b0), "r"(b1));
}

__global__ __launch_bounds__(THREADS, 4)
void spatial_emb_mma(const float* __restrict__ x,
                     const float* __restrict__ kern,
                     float* __restrict__ out) {
    __shared__ __align__(16) char smem[SMEM_BYTES];
    const uint32_t sb = smem_u32(smem);
    const int t = threadIdx.x, w = t >> 5, l = t & 31;
    const int c = blockIdx.x, bhalf = blockIdx.y;

    // ---- staging roles
    // x: 4 passes of 32 rows; lane row = t>>2 (+p*32), float col (t&3)*8 (2 float4)
    const float* xg = x + ((size_t)(bhalf * 128 + (t >> 2)) * C_DIM + c) * HW_DIM
                        + (size_t)(t & 3) * 8;
    const size_t xps = (size_t)32 * C_DIM * HW_DIM;   // 32 b-rows
    // k: row t>>3 (16 rows), float col (t&7)*4 (1 float4)
    const float* kg = kern + ((size_t)(t >> 3) * C_DIM + c) * HW_DIM
                           + (size_t)(t & 7) * 4;
    const uint32_t xoff0 = (uint32_t)(t >> 2) * XPITCH + (uint32_t)(t & 3) * 16;
    const uint32_t koff  = (uint32_t)(t >> 3) * XPITCH + (uint32_t)(t & 7) * 8;

    // ---- LDSM lane addressing (groups g = l>>3 pick the 4 8x8 matrices)
    const int li = l & 7;
    // A x4: m0=(r0-7,k0-7) m1=(r8-15,k0-7) m2=(r0-7,k8-15) m3=(r8-15,k8-15)
    const uint32_t rowA = (uint32_t)(w * 32 + ((l >> 3) & 1) * 8 + li);
    const uint32_t aoff = rowA * XPITCH + (uint32_t)(l >> 4) * 16;   // +mt*16*XPITCH +s*32
    // B x4: m0=(f0-7,k0-7) m1=(f0-7,k8-15) m2=(f8-15,k0-7) m3=(f8-15,k8-15)
    const uint32_t fB   = (uint32_t)(li + (l >> 4) * 8);
    const uint32_t boff = fB * XPITCH + (uint32_t)((l >> 3) & 1) * 16;  // +s*32

    float acc[2][2][4];
    #pragma unroll
    for (int mt = 0; mt < 2; mt++)
        #pragma unroll
        for (int nt = 0; nt < 2; nt++)
            #pragma unroll
            for (int i = 0; i < 4; i++)
                acc[mt][nt][i] = 0.0f;

    float4 xv[8], kv;
    // prologue: load chunk 0
    #pragma unroll
    for (int p = 0; p < 4; p++) {
        xv[2*p]   = *(const float4*)(xg + p * xps);
        xv[2*p+1] = *(const float4*)(xg + p * xps + 4);
    }
    kv = *(const float4*)(kg);

    for (int ch = 0; ch < NCH; ch++) {
        // ---- convert + store chunk ch to smem tiles
        #pragma unroll
        for (int p = 0; p < 4; p++) {
            uint32_t h[4], lo_[4];
            split2(xv[2*p].x,   xv[2*p].y,   h[0], lo_[0]);
            split2(xv[2*p].z,   xv[2*p].w,   h[1], lo_[1]);
            split2(xv[2*p+1].x, xv[2*p+1].y, h[2], lo_[2]);
            split2(xv[2*p+1].z, xv[2*p+1].w, h[3], lo_[3]);
            uint32_t o = xoff0 + (uint32_t)p * 32 * XPITCH;
            asm volatile("st.shared.v4.b32 [%0], {%1,%2,%3,%4};"
                :: "r"(sb + XHI + o), "r"(h[0]), "r"(h[1]), "r"(h[2]), "r"(h[3]) : "memory");
            asm volatile("st.shared.v4.b32 [%0], {%1,%2,%3,%4};"
                :: "r"(sb + XLO + o), "r"(lo_[0]), "r"(lo_[1]), "r"(lo_[2]), "r"(lo_[3]) : "memory");
        }
        {
            uint32_t h[2], lo_[2];
            split2(kv.x, kv.y, h[0], lo_[0]);
            split2(kv.z, kv.w, h[1], lo_[1]);
            asm volatile("st.shared.v2.b32 [%0], {%1,%2};"
                :: "r"(sb + KHI + koff), "r"(h[0]), "r"(h[1]) : "memory");
            asm volatile("st.shared.v2.b32 [%0], {%1,%2};"
                :: "r"(sb + KLO + koff), "r"(lo_[0]), "r"(lo_[1]) : "memory");
        }
        __syncthreads();   // tiles visible to all warps

        // ---- prefetch chunk ch+1 (flies during MMA compute)
        if (ch + 1 < NCH) {
            const float* xn = xg + (size_t)(ch + 1) * KC;
            #pragma unroll
            for (int p = 0; p < 4; p++) {
                xv[2*p]   = *(const float4*)(xn + p * xps);
                xv[2*p+1] = *(const float4*)(xn + p * xps + 4);
            }
            kv = *(const float4*)(kg + (size_t)(ch + 1) * KC);
        }

        // ---- compute: 2 k16-steps, 2 m-tiles, 2 n-tiles, 3-way split
        #pragma unroll
        for (int s = 0; s < 2; s++) {
            uint32_t bh_[4], bl_[4];
            ldsm4(bh_, sb + KHI + boff + s * 32);
            ldsm4(bl_, sb + KLO + boff + s * 32);
            #pragma unroll
            for (int mt = 0; mt < 2; mt++) {
                uint32_t ah_[4], al_[4];
                uint32_t aa = sb + XHI + aoff + (uint32_t)mt * 16 * XPITCH + s * 32;
                ldsm4(ah_, aa);
                ldsm4(al_, aa + (XLO - XHI));
                mma16816(acc[mt][0], ah_, bh_[0], bh_[1]);
                mma16816(acc[mt][0], al_, bh_[0], bh_[1]);
                mma16816(acc[mt][0], ah_, bl_[0], bl_[1]);
                mma16816(acc[mt][1], ah_, bh_[2], bh_[3]);
                mma16816(acc[mt][1], al_, bh_[2], bh_[3]);
                mma16816(acc[mt][1], ah_, bl_[2], bl_[3]);
            }
        }
        __syncthreads();   // all warps done reading before next overwrite
    }

    // ---- epilogue: C fragment (row l>>2 [+8], col (l&3)*2 [+1]) -> out[b, f*C + c]
    #pragma unroll
    for (int mt = 0; mt < 2; mt++) {
        #pragma unroll
        for (int nt = 0; nt < 2; nt++) {
            const int b0 = bhalf * 128 + w * 32 + mt * 16 + (l >> 2);
            const int f0 = nt * 8 + (l & 3) * 2;
            float* p0 = out + (size_t)b0 * (F_DIM * C_DIM) + (size_t)f0 * C_DIM + c;
            p0[0]      = acc[mt][nt][0];
            p0[C_DIM]  = acc[mt][nt][1];
            float* p1 = p0 + (size_t)8 * (F_DIM * C_DIM);
            p1[0]      = acc[mt][nt][2];
            p1[C_DIM]  = acc[mt][nt][3];
        }
    }
}

extern "C" void kernel_launch(void* const* d_in, const int* in_sizes, int n_in,
                              void* d_out, int out_size) {
    const float* x    = (const float*)d_in[0];
    const float* kern = (const float*)d_in[1];
    float* out        = (float*)d_out;

    dim3 grid(C_DIM, 2);
    spatial_emb_mma<<<grid, THREADS>>>(x, kern, out);
}